// round 4
// baseline (speedup 1.0000x reference)
#include <cuda_runtime.h>
#include <cuda_bf16.h>
#include <cstdint>

// EdgePrompt:
//   proj_src[n] = x[n,:] . W[0:128]
//   proj_dst[n] = x[n,:] . W[128:256]
//   out[e] = edge_weight[e] * sigmoid(proj_src[src[e]] + proj_dst[dst[e]] + b)
//
// Inputs (metadata order):
//   d_in[0]: x            float32 [50000*128]
//   d_in[1]: edge_index   int32   [2*500000]   (harness downcasts int64 -> int32)
//   d_in[2]: edge_weight  float32 [500000]
//   d_in[3]: W            float32 [256]
//   d_in[4]: b            float32 [1]
// Output: float32 [500000]

#define IN_DIM 128
#define MAX_NODES 50000

__device__ float g_proj_src[MAX_NODES];
__device__ float g_proj_dst[MAX_NODES];

// ---------------------------------------------------------------------------
// Kernel 1: warp-per-node projection.
// Each warp handles one node row (128 floats = 32 lanes x float4).
// Lane l holds W[4l..4l+3] and W[128+4l..128+4l+3] in registers.
// Row read is one fully-coalesced 512B transaction group per warp.
// ---------------------------------------------------------------------------
__global__ __launch_bounds__(256) void node_proj_kernel(
    const float* __restrict__ x,
    const float* __restrict__ W,
    int n_nodes)
{
    const int lane = threadIdx.x & 31;
    const int warp_in_blk = threadIdx.x >> 5;
    const int node = blockIdx.x * (blockDim.x >> 5) + warp_in_blk;
    if (node >= n_nodes) return;

    const float4* __restrict__ W4 = reinterpret_cast<const float4*>(W);
    const float4 wa = __ldg(&W4[lane]);        // W[0:128]
    const float4 wb = __ldg(&W4[32 + lane]);   // W[128:256]

    const float4* __restrict__ x4 = reinterpret_cast<const float4*>(x);
    const float4 v = __ldg(&x4[(size_t)node * 32 + lane]);

    float pa = v.x * wa.x + v.y * wa.y + v.z * wa.z + v.w * wa.w;
    float pb = v.x * wb.x + v.y * wb.y + v.z * wb.z + v.w * wb.w;

    #pragma unroll
    for (int off = 16; off > 0; off >>= 1) {
        pa += __shfl_xor_sync(0xFFFFFFFFu, pa, off);
        pb += __shfl_xor_sync(0xFFFFFFFFu, pb, off);
    }

    if (lane == 0) {
        g_proj_src[node] = pa;
        g_proj_dst[node] = pb;
    }
}

// ---------------------------------------------------------------------------
// Kernel 2: per-edge gather + sigmoid.
// proj arrays are 200KB each -> L2-resident; gathers hit L2, hidden by MLP.
// ---------------------------------------------------------------------------
__global__ __launch_bounds__(256) void edge_kernel(
    const int* __restrict__ edge_index,  // [2, E] int32
    const float* __restrict__ edge_weight,
    const float* __restrict__ b,
    float* __restrict__ out,
    int n_edges)
{
    const int e = blockIdx.x * blockDim.x + threadIdx.x;
    if (e >= n_edges) return;

    const int s = __ldg(&edge_index[e]);
    const int d = __ldg(&edge_index[n_edges + e]);

    const float logit = g_proj_src[s] + g_proj_dst[d] + b[0];
    const float sig = 1.0f / (1.0f + __expf(-logit));
    out[e] = __ldg(&edge_weight[e]) * sig;
}

extern "C" void kernel_launch(void* const* d_in, const int* in_sizes, int n_in,
                              void* d_out, int out_size)
{
    const float* x  = (const float*)d_in[0];
    const int*   ei = (const int*)d_in[1];
    const float* ew = (const float*)d_in[2];
    const float* W  = (const float*)d_in[3];
    const float* b  = (const float*)d_in[4];
    float* out = (float*)d_out;

    const int n_nodes = in_sizes[0] / IN_DIM;
    const int n_edges = in_sizes[2];

    const int warps_per_blk = 256 / 32;
    const int grid1 = (n_nodes + warps_per_blk - 1) / warps_per_blk;
    node_proj_kernel<<<grid1, 256>>>(x, W, n_nodes);

    const int grid2 = (n_edges + 255) / 256;
    edge_kernel<<<grid2, 256>>>(ei, ew, b, out, n_edges);
}

// round 9
// speedup vs baseline: 1.0151x; 1.0151x over previous
#include <cuda_runtime.h>
#include <cuda_bf16.h>
#include <cstdint>

// EdgePrompt:
//   proj_src[n] = x[n,:] . W[0:128]
//   proj_dst[n] = x[n,:] . W[128:256]
//   out[e] = edge_weight[e] * sigmoid(proj_src[src[e]] + proj_dst[dst[e]] + b)
//
// Inputs (metadata order):
//   d_in[0]: x            float32 [50000*128]
//   d_in[1]: edge_index   int32   [2*500000]
//   d_in[2]: edge_weight  float32 [500000]
//   d_in[3]: W            float32 [256]
//   d_in[4]: b            float32 [1]
// Output: float32 [500000]

#define IN_DIM 128
#define MAX_NODES 50000

__device__ float g_proj_src[MAX_NODES];
__device__ float g_proj_dst[MAX_NODES];

// ---------------------------------------------------------------------------
// Kernel 1: 8 lanes per node, 4 nodes per warp.
// Lane-in-group q loads float4s q, q+8, q+16, q+24 of the row:
// 4 independent LDG.128 per thread (MLP=4). Reduction is 3 shfl levels
// over the 8-lane group.
// ---------------------------------------------------------------------------
__global__ __launch_bounds__(256) void node_proj_kernel(
    const float* __restrict__ x,
    const float* __restrict__ W,
    int n_nodes)
{
    const int lane = threadIdx.x & 31;
    const int q    = lane & 7;        // lane within 8-lane group
    const int g    = lane >> 3;       // group 0..3
    const int warp_global = (blockIdx.x * blockDim.x + threadIdx.x) >> 5;
    const int node = warp_global * 4 + g;

    const float4* __restrict__ W4 = reinterpret_cast<const float4*>(W);
    const float4* __restrict__ x4 = reinterpret_cast<const float4*>(x);

    float pa = 0.0f, pb = 0.0f;
    if (node < n_nodes) {
        const size_t row = (size_t)node * 32;
        // Front-batch the 4 independent row loads
        float4 v0 = __ldg(&x4[row + q]);
        float4 v1 = __ldg(&x4[row + q + 8]);
        float4 v2 = __ldg(&x4[row + q + 16]);
        float4 v3 = __ldg(&x4[row + q + 24]);

        float4 wa0 = __ldg(&W4[q]);
        float4 wa1 = __ldg(&W4[q + 8]);
        float4 wa2 = __ldg(&W4[q + 16]);
        float4 wa3 = __ldg(&W4[q + 24]);
        float4 wb0 = __ldg(&W4[32 + q]);
        float4 wb1 = __ldg(&W4[32 + q + 8]);
        float4 wb2 = __ldg(&W4[32 + q + 16]);
        float4 wb3 = __ldg(&W4[32 + q + 24]);

        pa = v0.x*wa0.x + v0.y*wa0.y + v0.z*wa0.z + v0.w*wa0.w
           + v1.x*wa1.x + v1.y*wa1.y + v1.z*wa1.z + v1.w*wa1.w
           + v2.x*wa2.x + v2.y*wa2.y + v2.z*wa2.z + v2.w*wa2.w
           + v3.x*wa3.x + v3.y*wa3.y + v3.z*wa3.z + v3.w*wa3.w;
        pb = v0.x*wb0.x + v0.y*wb0.y + v0.z*wb0.z + v0.w*wb0.w
           + v1.x*wb1.x + v1.y*wb1.y + v1.z*wb1.z + v1.w*wb1.w
           + v2.x*wb2.x + v2.y*wb2.y + v2.z*wb2.z + v2.w*wb2.w
           + v3.x*wb3.x + v3.y*wb3.y + v3.z*wb3.z + v3.w*wb3.w;
    }

    // Reduce over the 8-lane group (xor stays within the group)
    #pragma unroll
    for (int off = 4; off > 0; off >>= 1) {
        pa += __shfl_xor_sync(0xFFFFFFFFu, pa, off);
        pb += __shfl_xor_sync(0xFFFFFFFFu, pb, off);
    }

    if (q == 0 && node < n_nodes) {
        g_proj_src[node] = pa;
        g_proj_dst[node] = pb;
    }
}

// ---------------------------------------------------------------------------
// Kernel 2: 4 edges per thread.
// Vectorized index/weight loads, then 8 independent L2-resident gathers
// front-batched for latency hiding (MLP ~11 per thread).
// ---------------------------------------------------------------------------
__global__ __launch_bounds__(256) void edge_kernel(
    const int* __restrict__ edge_index,   // [2, E] int32
    const float* __restrict__ edge_weight,
    const float* __restrict__ b,
    float* __restrict__ out,
    int n_edges)
{
    const int t = blockIdx.x * blockDim.x + threadIdx.x;
    const int e = t * 4;
    const float bb = __ldg(b);

    if (e + 3 < n_edges) {
        const int4   s4 = *reinterpret_cast<const int4*>(edge_index + e);
        const int4   d4 = *reinterpret_cast<const int4*>(edge_index + n_edges + e);
        const float4 w4 = *reinterpret_cast<const float4*>(edge_weight + e);

        // 8 independent gathers (L2-resident: proj arrays are 200KB each)
        const float ps0 = g_proj_src[s4.x];
        const float ps1 = g_proj_src[s4.y];
        const float ps2 = g_proj_src[s4.z];
        const float ps3 = g_proj_src[s4.w];
        const float pd0 = g_proj_dst[d4.x];
        const float pd1 = g_proj_dst[d4.y];
        const float pd2 = g_proj_dst[d4.z];
        const float pd3 = g_proj_dst[d4.w];

        float4 r;
        r.x = w4.x / (1.0f + __expf(-(ps0 + pd0 + bb)));
        r.y = w4.y / (1.0f + __expf(-(ps1 + pd1 + bb)));
        r.z = w4.z / (1.0f + __expf(-(ps2 + pd2 + bb)));
        r.w = w4.w / (1.0f + __expf(-(ps3 + pd3 + bb)));
        *reinterpret_cast<float4*>(out + e) = r;
    } else if (e < n_edges) {
        for (int i = e; i < n_edges; ++i) {
            const int s = __ldg(&edge_index[i]);
            const int d = __ldg(&edge_index[n_edges + i]);
            const float logit = g_proj_src[s] + g_proj_dst[d] + bb;
            out[i] = __ldg(&edge_weight[i]) / (1.0f + __expf(-logit));
        }
    }
}

extern "C" void kernel_launch(void* const* d_in, const int* in_sizes, int n_in,
                              void* d_out, int out_size)
{
    const float* x  = (const float*)d_in[0];
    const int*   ei = (const int*)d_in[1];
    const float* ew = (const float*)d_in[2];
    const float* W  = (const float*)d_in[3];
    const float* b  = (const float*)d_in[4];
    float* out = (float*)d_out;

    const int n_nodes = in_sizes[0] / IN_DIM;
    const int n_edges = in_sizes[2];

    // Kernel 1: 4 nodes per warp, 8 warps per block -> 32 nodes/block
    const int grid1 = (n_nodes + 31) / 32;
    node_proj_kernel<<<grid1, 256>>>(x, W, n_nodes);

    // Kernel 2: 4 edges per thread
    const int threads2 = (n_edges + 3) / 4;
    const int grid2 = (threads2 + 255) / 256;
    edge_kernel<<<grid2, 256>>>(ei, ew, b, out, n_edges);
}

// round 14
// speedup vs baseline: 1.0173x; 1.0022x over previous
#include <cuda_runtime.h>
#include <cuda_bf16.h>
#include <cstdint>

// EdgePrompt:
//   proj_src[n] = x[n,:] . W[0:128]
//   proj_dst[n] = x[n,:] . W[128:256]
//   out[e] = edge_weight[e] * sigmoid(proj_src[src[e]] + proj_dst[dst[e]] + b)
//
// Inputs (metadata order):
//   d_in[0]: x            float32 [50000*128]
//   d_in[1]: edge_index   int32   [2*500000]
//   d_in[2]: edge_weight  float32 [500000]
//   d_in[3]: W            float32 [256]
//   d_in[4]: b            float32 [1]
// Output: float32 [500000]

#define IN_DIM 128
#define MAX_NODES 50000

__device__ float g_proj_src[MAX_NODES];
__device__ float g_proj_dst[MAX_NODES];

// ---------------------------------------------------------------------------
// Kernel 1 (R4 measured-best): warp-per-node projection.
// Each warp handles one node row (128 floats = 32 lanes x float4).
// Maximum warp count (12.5k warps) saturates the DRAM stream.
// ---------------------------------------------------------------------------
__global__ __launch_bounds__(256) void node_proj_kernel(
    const float* __restrict__ x,
    const float* __restrict__ W,
    int n_nodes)
{
    const int lane = threadIdx.x & 31;
    const int warp_in_blk = threadIdx.x >> 5;
    const int node = blockIdx.x * (blockDim.x >> 5) + warp_in_blk;
    if (node >= n_nodes) return;

    const float4* __restrict__ W4 = reinterpret_cast<const float4*>(W);
    const float4 wa = __ldg(&W4[lane]);        // W[0:128]
    const float4 wb = __ldg(&W4[32 + lane]);   // W[128:256]

    const float4* __restrict__ x4 = reinterpret_cast<const float4*>(x);
    const float4 v = __ldg(&x4[(size_t)node * 32 + lane]);

    float pa = v.x * wa.x + v.y * wa.y + v.z * wa.z + v.w * wa.w;
    float pb = v.x * wb.x + v.y * wb.y + v.z * wb.z + v.w * wb.w;

    #pragma unroll
    for (int off = 16; off > 0; off >>= 1) {
        pa += __shfl_xor_sync(0xFFFFFFFFu, pa, off);
        pb += __shfl_xor_sync(0xFFFFFFFFu, pb, off);
    }

    if (lane == 0) {
        g_proj_src[node] = pa;
        g_proj_dst[node] = pb;
    }
}

// ---------------------------------------------------------------------------
// Kernel 2: 2 edges per thread — balance occupancy (250k threads, ~70% occ)
// against per-thread MLP (3 vector loads + 4 independent gathers ≈ 7).
// Latency-hiding product warps x MLP ≈ 2.3x the R9 version.
// ---------------------------------------------------------------------------
__global__ __launch_bounds__(256) void edge_kernel(
    const int* __restrict__ edge_index,   // [2, E] int32
    const float* __restrict__ edge_weight,
    const float* __restrict__ b,
    float* __restrict__ out,
    int n_edges)
{
    const int t = blockIdx.x * blockDim.x + threadIdx.x;
    const int e = t * 2;
    const float bb = __ldg(b);

    if (e + 1 < n_edges) {
        const int2   s2 = *reinterpret_cast<const int2*>(edge_index + e);
        const int2   d2 = *reinterpret_cast<const int2*>(edge_index + n_edges + e);
        const float2 w2 = *reinterpret_cast<const float2*>(edge_weight + e);

        // 4 independent gathers (proj arrays are 200KB each -> L2-resident)
        const float ps0 = g_proj_src[s2.x];
        const float ps1 = g_proj_src[s2.y];
        const float pd0 = g_proj_dst[d2.x];
        const float pd1 = g_proj_dst[d2.y];

        float2 r;
        r.x = w2.x / (1.0f + __expf(-(ps0 + pd0 + bb)));
        r.y = w2.y / (1.0f + __expf(-(ps1 + pd1 + bb)));
        *reinterpret_cast<float2*>(out + e) = r;
    } else if (e < n_edges) {
        for (int i = e; i < n_edges; ++i) {
            const int s = __ldg(&edge_index[i]);
            const int d = __ldg(&edge_index[n_edges + i]);
            const float logit = g_proj_src[s] + g_proj_dst[d] + bb;
            out[i] = __ldg(&edge_weight[i]) / (1.0f + __expf(-logit));
        }
    }
}

extern "C" void kernel_launch(void* const* d_in, const int* in_sizes, int n_in,
                              void* d_out, int out_size)
{
    const float* x  = (const float*)d_in[0];
    const int*   ei = (const int*)d_in[1];
    const float* ew = (const float*)d_in[2];
    const float* W  = (const float*)d_in[3];
    const float* b  = (const float*)d_in[4];
    float* out = (float*)d_out;

    const int n_nodes = in_sizes[0] / IN_DIM;
    const int n_edges = in_sizes[2];

    // Kernel 1: warp-per-node, 8 warps/block
    const int warps_per_blk = 256 / 32;
    const int grid1 = (n_nodes + warps_per_blk - 1) / warps_per_blk;
    node_proj_kernel<<<grid1, 256>>>(x, W, n_nodes);

    // Kernel 2: 2 edges per thread
    const int threads2 = (n_edges + 1) / 2;
    const int grid2 = (threads2 + 255) / 256;
    edge_kernel<<<grid2, 256>>>(ei, ew, b, out, n_edges);
}